// round 7
// baseline (speedup 1.0000x reference)
#include <cuda_runtime.h>
#include <math.h>
#include <stdint.h>

#define NP 500000
#define NQ 200000
#define CDIM 64
#define EMAX 1200000

// padded sizes for the 1024-per-block scan
#define NQPAD 200704   // 196 * 1024
#define NPPAD 500736   // 489 * 1024
#define MQ 196
#define MP 489

// ------------------------- scratch (static device globals) -------------------------
__device__ float g_hsP[(size_t)NP * CDIM];
__device__ float g_hsQ[(size_t)NQ * CDIM];
__device__ float g_hp1[(size_t)NP * CDIM];
__device__ float g_hq1[(size_t)NQ * CDIM];
__device__ float g_alsP[NP], g_aldP[NP];
__device__ float g_alsQ[NQ], g_aldQ[NQ];
__device__ float g_wvec[128];
// CSR scratch
__device__ int g_cntQ[NQPAD], g_cntP[NPPAD];
__device__ int g_rowQ[NQPAD], g_rowP[NPPAD];
__device__ int g_curQ[NQPAD], g_curP[NPPAD];
__device__ int g_partQ[1024], g_partP[1024];
__device__ int g_ssrc0[EMAX];   // conv0 (P->Q): person srcs sorted by product dst
__device__ int g_ssrc1[EMAX];   // conv1 (Q->P): product srcs sorted by person dst

// ------------------------- f32x2 packed-FMA helpers -------------------------
__device__ __forceinline__ unsigned long long pack2(float lo, float hi) {
    unsigned long long r;
    asm("mov.b64 %0, {%1, %2};" : "=l"(r) : "f"(lo), "f"(hi));
    return r;
}
__device__ __forceinline__ void fma2(unsigned long long& acc, unsigned long long a,
                                     unsigned long long b) {
    asm("fma.rn.f32x2 %0, %1, %2, %0;" : "+l"(acc) : "l"(a), "l"(b));
}
__device__ __forceinline__ float2 unpack2(unsigned long long v) {
    float lo, hi;
    asm("mov.b64 {%0, %1}, %2;" : "=f"(lo), "=f"(hi) : "l"(v));
    return make_float2(lo, hi);
}

// ------------------------- CSR build kernels -------------------------
__global__ void zero_kernel(int* __restrict__ cQ, int* __restrict__ cP) {
    int i = blockIdx.x * blockDim.x + threadIdx.x;
    if (i < NQPAD) cQ[i] = 0;
    else if (i < NQPAD + NPPAD) cP[i - NQPAD] = 0;
}

__global__ void hist_kernel(const int* __restrict__ pv_d, const int* __restrict__ vp_d,
                            int* __restrict__ cntQ, int* __restrict__ cntP, int E) {
    int i = blockIdx.x * blockDim.x + threadIdx.x;
    if (i < E) atomicAdd(&cntQ[__ldg(&pv_d[i])], 1);
    else if (i < 2 * E) atomicAdd(&cntP[__ldg(&vp_d[i - E])], 1);
}

__global__ void scan_local_kernel(const int* __restrict__ cnt, int* __restrict__ row,
                                  int* __restrict__ part) {
    __shared__ int sm[256];
    int t = threadIdx.x;
    int base = blockIdx.x * 1024 + t * 4;
    int4 v = *(const int4*)(cnt + base);
    int tsum = v.x + v.y + v.z + v.w;
    sm[t] = tsum;
    __syncthreads();
    #pragma unroll
    for (int off = 1; off < 256; off <<= 1) {
        int add = (t >= off) ? sm[t - off] : 0;
        __syncthreads();
        sm[t] += add;
        __syncthreads();
    }
    int excl = sm[t] - tsum;
    int r1 = excl + v.x, r2 = r1 + v.y, r3 = r2 + v.z;
    *(int4*)(row + base) = make_int4(excl, r1, r2, r3);
    if (t == 255) part[blockIdx.x] = sm[255];
}

__global__ void scan_part_kernel(int* __restrict__ part, int M) {
    __shared__ int sm[1024];
    int t = threadIdx.x;
    int orig = (t < M) ? part[t] : 0;
    sm[t] = orig;
    __syncthreads();
    #pragma unroll
    for (int off = 1; off < 1024; off <<= 1) {
        int add = (t >= off) ? sm[t - off] : 0;
        __syncthreads();
        sm[t] += add;
        __syncthreads();
    }
    if (t < M) part[t] = sm[t] - orig;
}

__global__ void scan_add_kernel(int* __restrict__ row, const int* __restrict__ part,
                                int* __restrict__ cur, int Npad) {
    int i = blockIdx.x * blockDim.x + threadIdx.x;
    if (i >= Npad) return;
    int r = row[i] + __ldg(&part[i >> 10]);
    row[i] = r;
    cur[i] = r;
}

__global__ void scatter_kernel(const int* __restrict__ pv_s, const int* __restrict__ pv_d,
                               const int* __restrict__ vp_s, const int* __restrict__ vp_d,
                               int* __restrict__ curQ, int* __restrict__ curP,
                               int* __restrict__ ssrc0, int* __restrict__ ssrc1, int E) {
    int i = blockIdx.x * blockDim.x + threadIdx.x;
    if (i < E) {
        int pos = atomicAdd(&curQ[__ldg(&pv_d[i])], 1);
        ssrc0[pos] = __ldg(&pv_s[i]);
    } else if (i < 2 * E) {
        int j = i - E;
        int pos = atomicAdd(&curP[__ldg(&vp_d[j])], 1);
        ssrc1[pos] = __ldg(&vp_s[j]);
    }
}

// ------------------------- dense kernels (R2-proven) -------------------------
__global__ void wvec2_kernel(const float* __restrict__ Wd0, const float* __restrict__ Wd1,
                             const float* __restrict__ avd0, const float* __restrict__ avd1,
                             float* __restrict__ wvec) {
    int t = threadIdx.x;
    const float* W = (t < 64) ? Wd0 : Wd1;
    const float* a = (t < 64) ? avd0 : avd1;
    int k = t & 63;
    float s = 0.f;
    #pragma unroll
    for (int c = 0; c < CDIM; c++) s = fmaf(W[k * CDIM + c], a[c], s);
    wvec[t] = s;
}

template <bool ELU>
__global__ __launch_bounds__(128) void gemm_kernel(
    const float* __restrict__ X, const float* __restrict__ W,
    const float* __restrict__ avs, const float* __restrict__ wvec,
    float* __restrict__ H, float* __restrict__ als, float* __restrict__ ald, int N)
{
    __shared__ float xT[64 * 128];
    __shared__ float ws[64 * 64];
    const int tid  = threadIdx.x;
    const int row0 = blockIdx.x * 128;

    {
        const float4* Wv = (const float4*)W;
        float4* wsv = (float4*)ws;
        #pragma unroll
        for (int i = 0; i < 8; i++) wsv[i * 128 + tid] = Wv[i * 128 + tid];
    }
    {
        int row = row0 + tid;
        if (row < N) {
            const float4* Xv = (const float4*)(X + (size_t)row * CDIM);
            #pragma unroll
            for (int j = 0; j < 16; j++) {
                float4 v = Xv[j];
                if (ELU) {
                    v.x = (v.x > 0.f) ? v.x : expm1f(v.x);
                    v.y = (v.y > 0.f) ? v.y : expm1f(v.y);
                    v.z = (v.z > 0.f) ? v.z : expm1f(v.z);
                    v.w = (v.w > 0.f) ? v.w : expm1f(v.w);
                }
                xT[(4 * j + 0) * 128 + tid] = v.x;
                xT[(4 * j + 1) * 128 + tid] = v.y;
                xT[(4 * j + 2) * 128 + tid] = v.z;
                xT[(4 * j + 3) * 128 + tid] = v.w;
            }
        } else {
            #pragma unroll
            for (int j = 0; j < 64; j++) xT[j * 128 + tid] = 0.f;
        }
    }
    __syncthreads();

    const int ty = tid >> 3;
    const int tx = tid & 7;
    unsigned long long acc[8][4];
    #pragma unroll
    for (int i = 0; i < 8; i++)
        #pragma unroll
        for (int j = 0; j < 4; j++) acc[i][j] = 0ull;

    #pragma unroll 4
    for (int k = 0; k < 64; k++) {
        float4 a0 = *(const float4*)&xT[k * 128 + ty * 8];
        float4 a1 = *(const float4*)&xT[k * 128 + ty * 8 + 4];
        float4 b0 = *(const float4*)&ws[k * 64 + tx * 8];
        float4 b1 = *(const float4*)&ws[k * 64 + tx * 8 + 4];
        unsigned long long bp[4] = {pack2(b0.x, b0.y), pack2(b0.z, b0.w),
                                    pack2(b1.x, b1.y), pack2(b1.z, b1.w)};
        float a[8] = {a0.x, a0.y, a0.z, a0.w, a1.x, a1.y, a1.z, a1.w};
        #pragma unroll
        for (int i = 0; i < 8; i++) {
            unsigned long long ap = pack2(a[i], a[i]);
            #pragma unroll
            for (int j = 0; j < 4; j++) fma2(acc[i][j], ap, bp[j]);
        }
    }

    unsigned long long avp[4];
    {
        float4 av0 = __ldg((const float4*)avs + tx * 2);
        float4 av1 = __ldg((const float4*)avs + tx * 2 + 1);
        avp[0] = pack2(av0.x, av0.y); avp[1] = pack2(av0.z, av0.w);
        avp[2] = pack2(av1.x, av1.y); avp[3] = pack2(av1.z, av1.w);
    }

    #pragma unroll
    for (int i = 0; i < 8; i++) {
        int row = row0 + ty * 8 + i;
        unsigned long long alp = 0ull;
        #pragma unroll
        for (int j = 0; j < 4; j++) fma2(alp, acc[i][j], avp[j]);
        float2 f = unpack2(alp);
        float al = f.x + f.y;
        al += __shfl_down_sync(0xffffffffu, al, 4);
        al += __shfl_down_sync(0xffffffffu, al, 2);
        al += __shfl_down_sync(0xffffffffu, al, 1);
        if (row < N) {
            ulonglong2* Hp = (ulonglong2*)(H + (size_t)row * CDIM + tx * 8);
            Hp[0] = make_ulonglong2(acc[i][0], acc[i][1]);
            Hp[1] = make_ulonglong2(acc[i][2], acc[i][3]);
            if (tx == 0) als[row] = al;
        }
    }

    {
        float s = 0.f;
        #pragma unroll
        for (int k = 0; k < 64; k++) s = fmaf(xT[k * 128 + tid], __ldg(&wvec[k]), s);
        int row = row0 + tid;
        if (row < N) ald[row] = s;
    }
}

// ---------------- CSR GAT: single pass, half-warp (16 lanes x float4) per dst row ----
// out[d] = (elu?)( bias + (1/Σex)·Σ ex_e·hs[src_e] ),  ex = exp(lrelu(als[src]+ald[d]))
template <bool ELUOUT>
__global__ __launch_bounds__(256) void gat_kernel(
    const int* __restrict__ row, const int* __restrict__ cnt, const int* __restrict__ ssrc,
    const float* __restrict__ als, const float* __restrict__ ald,
    const float* __restrict__ hs, const float* __restrict__ bias,
    float* __restrict__ out, int Nd)
{
    int hw = (blockIdx.x * blockDim.x + threadIdx.x) >> 4;   // half-warp id = dst row
    if (hw >= Nd) return;
    const int lane = threadIdx.x & 15;
    const unsigned FULL = 0xffffffffu;

    int start = __ldg(&row[hw]);
    int deg   = __ldg(&cnt[hw]);
    float4 res = __ldg((const float4*)bias + lane);

    if (deg > 0) {
        float aldv = __ldg(&ald[hw]);
        float4 acc = make_float4(0.f, 0.f, 0.f, 0.f);
        float den = 0.f;
        for (int c0 = 0; c0 < deg; c0 += 16) {
            int e = c0 + lane;
            int s = 0; float ex = 0.f;
            if (e < deg) {
                s = __ldg(&ssrc[start + e]);
                float v = __ldg(&als[s]) + aldv;
                v = (v >= 0.f) ? v : 0.2f * v;
                ex = __expf(fminf(v, 80.f));
            }
            {   // den partial: reduce ex over the 16-lane group
                float exr = ex;
                #pragma unroll
                for (int off = 8; off > 0; off >>= 1)
                    exr += __shfl_xor_sync(FULL, exr, off, 16);
                den += exr;
            }
            int m = min(16, deg - c0);
            int j = 0;
            for (; j + 4 <= m; j += 4) {
                float a0 = __shfl_sync(FULL, ex, j + 0, 16); int s0 = __shfl_sync(FULL, s, j + 0, 16);
                float a1 = __shfl_sync(FULL, ex, j + 1, 16); int s1 = __shfl_sync(FULL, s, j + 1, 16);
                float a2 = __shfl_sync(FULL, ex, j + 2, 16); int s2 = __shfl_sync(FULL, s, j + 2, 16);
                float a3 = __shfl_sync(FULL, ex, j + 3, 16); int s3 = __shfl_sync(FULL, s, j + 3, 16);
                float4 h0 = __ldg((const float4*)(hs + (size_t)s0 * CDIM) + lane);
                float4 h1 = __ldg((const float4*)(hs + (size_t)s1 * CDIM) + lane);
                float4 h2 = __ldg((const float4*)(hs + (size_t)s2 * CDIM) + lane);
                float4 h3 = __ldg((const float4*)(hs + (size_t)s3 * CDIM) + lane);
                acc.x = fmaf(a0, h0.x, acc.x); acc.y = fmaf(a0, h0.y, acc.y);
                acc.z = fmaf(a0, h0.z, acc.z); acc.w = fmaf(a0, h0.w, acc.w);
                acc.x = fmaf(a1, h1.x, acc.x); acc.y = fmaf(a1, h1.y, acc.y);
                acc.z = fmaf(a1, h1.z, acc.z); acc.w = fmaf(a1, h1.w, acc.w);
                acc.x = fmaf(a2, h2.x, acc.x); acc.y = fmaf(a2, h2.y, acc.y);
                acc.z = fmaf(a2, h2.z, acc.z); acc.w = fmaf(a2, h2.w, acc.w);
                acc.x = fmaf(a3, h3.x, acc.x); acc.y = fmaf(a3, h3.y, acc.y);
                acc.z = fmaf(a3, h3.z, acc.z); acc.w = fmaf(a3, h3.w, acc.w);
            }
            for (; j < m; j++) {
                float a0 = __shfl_sync(FULL, ex, j, 16); int s0 = __shfl_sync(FULL, s, j, 16);
                float4 h0 = __ldg((const float4*)(hs + (size_t)s0 * CDIM) + lane);
                acc.x = fmaf(a0, h0.x, acc.x); acc.y = fmaf(a0, h0.y, acc.y);
                acc.z = fmaf(a0, h0.z, acc.z); acc.w = fmaf(a0, h0.w, acc.w);
            }
        }
        float inv = 1.f / den;
        res.x = fmaf(acc.x, inv, res.x); res.y = fmaf(acc.y, inv, res.y);
        res.z = fmaf(acc.z, inv, res.z); res.w = fmaf(acc.w, inv, res.w);
    }
    if (ELUOUT) {
        res.x = (res.x > 0.f) ? res.x : expm1f(res.x);
        res.y = (res.y > 0.f) ? res.y : expm1f(res.y);
        res.z = (res.z > 0.f) ? res.z : expm1f(res.z);
        res.w = (res.w > 0.f) ? res.w : expm1f(res.w);
    }
    ((float4*)(out + (size_t)hw * CDIM))[lane] = res;
}

// ------------------------- host orchestration -------------------------
extern "C" void kernel_launch(void* const* d_in, const int* in_sizes, int n_in,
                              void* d_out, int out_size)
{
    const float* xp   = (const float*)d_in[0];
    const float* xq   = (const float*)d_in[1];
    const int*   pv_s = (const int*)d_in[2];
    const int*   pv_d = (const int*)d_in[3];
    const int*   vp_s = (const int*)d_in[4];
    const int*   vp_d = (const int*)d_in[5];
    const float* Wsrc = (const float*)d_in[6];
    const float* Wdst = (const float*)d_in[7];
    const float* asrc = (const float*)d_in[8];
    const float* adst = (const float*)d_in[9];
    const float* bias = (const float*)d_in[10];
    int E = in_sizes[2];

    float *hsP, *hsQ, *hp1, *hq1, *alsP, *aldP, *alsQ, *aldQ, *wvec;
    int *cntQ, *cntP, *rowQ, *rowP, *curQ, *curP, *partQ, *partP, *ssrc0, *ssrc1;
    cudaGetSymbolAddress((void**)&hsP,   g_hsP);
    cudaGetSymbolAddress((void**)&hsQ,   g_hsQ);
    cudaGetSymbolAddress((void**)&hp1,   g_hp1);
    cudaGetSymbolAddress((void**)&hq1,   g_hq1);
    cudaGetSymbolAddress((void**)&alsP,  g_alsP);
    cudaGetSymbolAddress((void**)&aldP,  g_aldP);
    cudaGetSymbolAddress((void**)&alsQ,  g_alsQ);
    cudaGetSymbolAddress((void**)&aldQ,  g_aldQ);
    cudaGetSymbolAddress((void**)&wvec,  g_wvec);
    cudaGetSymbolAddress((void**)&cntQ,  g_cntQ);
    cudaGetSymbolAddress((void**)&cntP,  g_cntP);
    cudaGetSymbolAddress((void**)&rowQ,  g_rowQ);
    cudaGetSymbolAddress((void**)&rowP,  g_rowP);
    cudaGetSymbolAddress((void**)&curQ,  g_curQ);
    cudaGetSymbolAddress((void**)&curP,  g_curP);
    cudaGetSymbolAddress((void**)&partQ, g_partQ);
    cudaGetSymbolAddress((void**)&partP, g_partP);
    cudaGetSymbolAddress((void**)&ssrc0, g_ssrc0);
    cudaGetSymbolAddress((void**)&ssrc1, g_ssrc1);

    float* outp = (float*)d_out;
    float* outq = (float*)d_out + (size_t)NP * CDIM;

    const unsigned gP  = (NP + 127) / 128, gQ = (NQ + 127) / 128;
    const unsigned gGP = (unsigned)(((long)NP * 16 + 255) / 256);
    const unsigned gGQ = (unsigned)(((long)NQ * 16 + 255) / 256);
    const unsigned gE2 = (2 * E + 255) / 256;

    // ---- CSR build (once; reused by both layers) ----
    zero_kernel<<<(NQPAD + NPPAD + 255) / 256, 256>>>(cntQ, cntP);
    hist_kernel<<<gE2, 256>>>(pv_d, vp_d, cntQ, cntP, E);
    scan_local_kernel<<<MQ, 256>>>(cntQ, rowQ, partQ);
    scan_local_kernel<<<MP, 256>>>(cntP, rowP, partP);
    scan_part_kernel<<<1, 1024>>>(partQ, MQ);
    scan_part_kernel<<<1, 1024>>>(partP, MP);
    scan_add_kernel<<<NQPAD / 256, 256>>>(rowQ, partQ, curQ, NQPAD);
    scan_add_kernel<<<NPPAD / 256, 256>>>(rowP, partP, curP, NPPAD);
    scatter_kernel<<<gE2, 256>>>(pv_s, pv_d, vp_s, vp_d, curQ, curP, ssrc0, ssrc1, E);

    // ---- layer 0 ----
    wvec2_kernel<<<1, 128>>>(Wdst + 0 * 4096, Wdst + 1 * 4096, adst + 0 * 64, adst + 1 * 64, wvec);
    gemm_kernel<false><<<gP, 128>>>(xp, Wsrc + 0 * 4096, asrc + 0 * 64, wvec + 64,
                                    hsP, alsP, aldP, NP);
    gemm_kernel<false><<<gQ, 128>>>(xq, Wsrc + 1 * 4096, asrc + 1 * 64, wvec,
                                    hsQ, alsQ, aldQ, NQ);
    // conv1 first (hsQ L2-hot), then conv0
    gat_kernel<false><<<gGP, 256>>>(rowP, cntP, ssrc1, alsQ, aldP, hsQ, bias + 1 * 64, hp1, NP);
    gat_kernel<false><<<gGQ, 256>>>(rowQ, cntQ, ssrc0, alsP, aldQ, hsP, bias + 0 * 64, hq1, NQ);

    // ---- layer 1 (ELU on load; ELU folded into output store) ----
    wvec2_kernel<<<1, 128>>>(Wdst + 2 * 4096, Wdst + 3 * 4096, adst + 2 * 64, adst + 3 * 64, wvec);
    gemm_kernel<true><<<gP, 128>>>(hp1, Wsrc + 2 * 4096, asrc + 2 * 64, wvec + 64,
                                   hsP, alsP, aldP, NP);
    gemm_kernel<true><<<gQ, 128>>>(hq1, Wsrc + 3 * 4096, asrc + 3 * 64, wvec,
                                   hsQ, alsQ, aldQ, NQ);
    gat_kernel<true><<<gGP, 256>>>(rowP, cntP, ssrc1, alsQ, aldP, hsQ, bias + 3 * 64, outp, NP);
    gat_kernel<true><<<gGQ, 256>>>(rowQ, cntQ, ssrc0, alsP, aldQ, hsP, bias + 2 * 64, outq, NQ);
}

// round 8
// speedup vs baseline: 1.1478x; 1.1478x over previous
#include <cuda_runtime.h>
#include <math.h>
#include <stdint.h>

#define NP 500000
#define NQ 200000
#define CDIM 64
#define EMAX 1200000

// padded sizes for the 1024-per-block scan
#define NQPAD 200704   // 196 * 1024
#define NPPAD 500736   // 489 * 1024
#define MQ 196
#define MP 489

// ------------------------- scratch (static device globals) -------------------------
__device__ float g_hsP[(size_t)NP * CDIM];
__device__ float g_hsQ[(size_t)NQ * CDIM];
__device__ float g_hp1[(size_t)NP * CDIM];
__device__ float g_hq1[(size_t)NQ * CDIM];
__device__ float g_alsP[NP], g_aldP[NP];
__device__ float g_alsQ[NQ], g_aldQ[NQ];
__device__ float g_wvec[128];
// CSR scratch
__device__ int g_cntQ[NQPAD], g_cntP[NPPAD];
__device__ int g_rowQ[NQPAD], g_rowP[NPPAD];
__device__ int g_curQ[NQPAD], g_curP[NPPAD];
__device__ int g_partQ[1024], g_partP[1024];
__device__ int g_ssrc0[EMAX];   // conv0 (P->Q): person srcs sorted by product dst
__device__ int g_ssrc1[EMAX];   // conv1 (Q->P): product srcs sorted by person dst

// ------------------------- f32x2 packed-FMA helpers -------------------------
__device__ __forceinline__ unsigned long long pack2(float lo, float hi) {
    unsigned long long r;
    asm("mov.b64 %0, {%1, %2};" : "=l"(r) : "f"(lo), "f"(hi));
    return r;
}
__device__ __forceinline__ void fma2(unsigned long long& acc, unsigned long long a,
                                     unsigned long long b) {
    asm("fma.rn.f32x2 %0, %1, %2, %0;" : "+l"(acc) : "l"(a), "l"(b));
}
__device__ __forceinline__ float2 unpack2(unsigned long long v) {
    float lo, hi;
    asm("mov.b64 {%0, %1}, %2;" : "=f"(lo), "=f"(hi) : "l"(v));
    return make_float2(lo, hi);
}

// ------------------------- CSR build kernels -------------------------
__global__ void zero_kernel(int* __restrict__ cQ, int* __restrict__ cP) {
    int i = blockIdx.x * blockDim.x + threadIdx.x;
    if (i < NQPAD) cQ[i] = 0;
    else if (i < NQPAD + NPPAD) cP[i - NQPAD] = 0;
}

__global__ void hist_kernel(const int* __restrict__ pv_d, const int* __restrict__ vp_d,
                            int* __restrict__ cntQ, int* __restrict__ cntP, int E) {
    int i = blockIdx.x * blockDim.x + threadIdx.x;
    if (i < E) atomicAdd(&cntQ[__ldg(&pv_d[i])], 1);
    else if (i < 2 * E) atomicAdd(&cntP[__ldg(&vp_d[i - E])], 1);
}

__global__ void scan_local_kernel(const int* __restrict__ cnt, int* __restrict__ row,
                                  int* __restrict__ part) {
    __shared__ int sm[256];
    int t = threadIdx.x;
    int base = blockIdx.x * 1024 + t * 4;
    int4 v = *(const int4*)(cnt + base);
    int tsum = v.x + v.y + v.z + v.w;
    sm[t] = tsum;
    __syncthreads();
    #pragma unroll
    for (int off = 1; off < 256; off <<= 1) {
        int add = (t >= off) ? sm[t - off] : 0;
        __syncthreads();
        sm[t] += add;
        __syncthreads();
    }
    int excl = sm[t] - tsum;
    int r1 = excl + v.x, r2 = r1 + v.y, r3 = r2 + v.z;
    *(int4*)(row + base) = make_int4(excl, r1, r2, r3);
    if (t == 255) part[blockIdx.x] = sm[255];
}

__global__ void scan_part_kernel(int* __restrict__ part, int M) {
    __shared__ int sm[1024];
    int t = threadIdx.x;
    int orig = (t < M) ? part[t] : 0;
    sm[t] = orig;
    __syncthreads();
    #pragma unroll
    for (int off = 1; off < 1024; off <<= 1) {
        int add = (t >= off) ? sm[t - off] : 0;
        __syncthreads();
        sm[t] += add;
        __syncthreads();
    }
    if (t < M) part[t] = sm[t] - orig;
}

__global__ void scan_add_kernel(int* __restrict__ row, const int* __restrict__ part,
                                int* __restrict__ cur, int Npad) {
    int i = blockIdx.x * blockDim.x + threadIdx.x;
    if (i >= Npad) return;
    int r = row[i] + __ldg(&part[i >> 10]);
    row[i] = r;
    cur[i] = r;
}

__global__ void scatter_kernel(const int* __restrict__ pv_s, const int* __restrict__ pv_d,
                               const int* __restrict__ vp_s, const int* __restrict__ vp_d,
                               int* __restrict__ curQ, int* __restrict__ curP,
                               int* __restrict__ ssrc0, int* __restrict__ ssrc1, int E) {
    int i = blockIdx.x * blockDim.x + threadIdx.x;
    if (i < E) {
        int pos = atomicAdd(&curQ[__ldg(&pv_d[i])], 1);
        ssrc0[pos] = __ldg(&pv_s[i]);
    } else if (i < 2 * E) {
        int j = i - E;
        int pos = atomicAdd(&curP[__ldg(&vp_d[j])], 1);
        ssrc1[pos] = __ldg(&vp_s[j]);
    }
}

// ------------------------- dense kernels (R2-proven) -------------------------
__global__ void wvec2_kernel(const float* __restrict__ Wd0, const float* __restrict__ Wd1,
                             const float* __restrict__ avd0, const float* __restrict__ avd1,
                             float* __restrict__ wvec) {
    int t = threadIdx.x;
    const float* W = (t < 64) ? Wd0 : Wd1;
    const float* a = (t < 64) ? avd0 : avd1;
    int k = t & 63;
    float s = 0.f;
    #pragma unroll
    for (int c = 0; c < CDIM; c++) s = fmaf(W[k * CDIM + c], a[c], s);
    wvec[t] = s;
}

template <bool ELU>
__global__ __launch_bounds__(128) void gemm_kernel(
    const float* __restrict__ X, const float* __restrict__ W,
    const float* __restrict__ avs, const float* __restrict__ wvec,
    float* __restrict__ H, float* __restrict__ als, float* __restrict__ ald, int N)
{
    __shared__ float xT[64 * 128];
    __shared__ float ws[64 * 64];
    const int tid  = threadIdx.x;
    const int row0 = blockIdx.x * 128;

    {
        const float4* Wv = (const float4*)W;
        float4* wsv = (float4*)ws;
        #pragma unroll
        for (int i = 0; i < 8; i++) wsv[i * 128 + tid] = Wv[i * 128 + tid];
    }
    {
        int row = row0 + tid;
        if (row < N) {
            const float4* Xv = (const float4*)(X + (size_t)row * CDIM);
            #pragma unroll
            for (int j = 0; j < 16; j++) {
                float4 v = Xv[j];
                if (ELU) {
                    v.x = (v.x > 0.f) ? v.x : expm1f(v.x);
                    v.y = (v.y > 0.f) ? v.y : expm1f(v.y);
                    v.z = (v.z > 0.f) ? v.z : expm1f(v.z);
                    v.w = (v.w > 0.f) ? v.w : expm1f(v.w);
                }
                xT[(4 * j + 0) * 128 + tid] = v.x;
                xT[(4 * j + 1) * 128 + tid] = v.y;
                xT[(4 * j + 2) * 128 + tid] = v.z;
                xT[(4 * j + 3) * 128 + tid] = v.w;
            }
        } else {
            #pragma unroll
            for (int j = 0; j < 64; j++) xT[j * 128 + tid] = 0.f;
        }
    }
    __syncthreads();

    const int ty = tid >> 3;
    const int tx = tid & 7;
    unsigned long long acc[8][4];
    #pragma unroll
    for (int i = 0; i < 8; i++)
        #pragma unroll
        for (int j = 0; j < 4; j++) acc[i][j] = 0ull;

    #pragma unroll 4
    for (int k = 0; k < 64; k++) {
        float4 a0 = *(const float4*)&xT[k * 128 + ty * 8];
        float4 a1 = *(const float4*)&xT[k * 128 + ty * 8 + 4];
        float4 b0 = *(const float4*)&ws[k * 64 + tx * 8];
        float4 b1 = *(const float4*)&ws[k * 64 + tx * 8 + 4];
        unsigned long long bp[4] = {pack2(b0.x, b0.y), pack2(b0.z, b0.w),
                                    pack2(b1.x, b1.y), pack2(b1.z, b1.w)};
        float a[8] = {a0.x, a0.y, a0.z, a0.w, a1.x, a1.y, a1.z, a1.w};
        #pragma unroll
        for (int i = 0; i < 8; i++) {
            unsigned long long ap = pack2(a[i], a[i]);
            #pragma unroll
            for (int j = 0; j < 4; j++) fma2(acc[i][j], ap, bp[j]);
        }
    }

    unsigned long long avp[4];
    {
        float4 av0 = __ldg((const float4*)avs + tx * 2);
        float4 av1 = __ldg((const float4*)avs + tx * 2 + 1);
        avp[0] = pack2(av0.x, av0.y); avp[1] = pack2(av0.z, av0.w);
        avp[2] = pack2(av1.x, av1.y); avp[3] = pack2(av1.z, av1.w);
    }

    #pragma unroll
    for (int i = 0; i < 8; i++) {
        int row = row0 + ty * 8 + i;
        unsigned long long alp = 0ull;
        #pragma unroll
        for (int j = 0; j < 4; j++) fma2(alp, acc[i][j], avp[j]);
        float2 f = unpack2(alp);
        float al = f.x + f.y;
        al += __shfl_down_sync(0xffffffffu, al, 4);
        al += __shfl_down_sync(0xffffffffu, al, 2);
        al += __shfl_down_sync(0xffffffffu, al, 1);
        if (row < N) {
            ulonglong2* Hp = (ulonglong2*)(H + (size_t)row * CDIM + tx * 8);
            Hp[0] = make_ulonglong2(acc[i][0], acc[i][1]);
            Hp[1] = make_ulonglong2(acc[i][2], acc[i][3]);
            if (tx == 0) als[row] = al;
        }
    }

    {
        float s = 0.f;
        #pragma unroll
        for (int k = 0; k < 64; k++) s = fmaf(xT[k * 128 + tid], __ldg(&wvec[k]), s);
        int row = row0 + tid;
        if (row < N) ald[row] = s;
    }
}

// ---------------- CSR GAT: warp per dst row, single pass, paired-edge float4 gather ----
// out[d] = (elu?)( bias + (1/Σex)·Σ ex_e·hs[src_e] ),  ex = exp(lrelu(als[src]+ald[d]))
// Per gather iteration: lanes 0-15 fetch edge j's row (float4/lane), lanes 16-31 edge j+1.
// All shfls are full-warp, loop bounds warp-uniform -> no divergence.
template <bool ELUOUT>
__global__ __launch_bounds__(256) void gat_kernel(
    const int* __restrict__ row, const int* __restrict__ cnt, const int* __restrict__ ssrc,
    const float* __restrict__ als, const float* __restrict__ ald,
    const float* __restrict__ hs, const float* __restrict__ bias,
    float* __restrict__ out, int Nd)
{
    const unsigned FULL = 0xffffffffu;
    int w = (blockIdx.x * blockDim.x + threadIdx.x) >> 5;   // warp id = dst row
    if (w >= Nd) return;
    const int lane = threadIdx.x & 31;
    const int half = lane >> 4;      // 0: edge j, 1: edge j+1
    const int part = lane & 15;      // float4 index within row

    int start = __ldg(&row[w]);
    int deg   = __ldg(&cnt[w]);
    float4 res = __ldg((const float4*)bias + part);

    if (deg > 0) {
        float aldv = __ldg(&ald[w]);
        float4 acc = make_float4(0.f, 0.f, 0.f, 0.f);
        float den = 0.f;
        for (int c0 = 0; c0 < deg; c0 += 32) {
            int e = c0 + lane;
            int s = 0; float ex = 0.f;
            if (e < deg) {
                s = __ldg(&ssrc[start + e]);
                float v = __ldg(&als[s]) + aldv;
                v = (v >= 0.f) ? v : 0.2f * v;
                ex = __expf(fminf(v, 80.f));
            }
            // den: full-warp reduction of this chunk
            float exr = ex;
            #pragma unroll
            for (int off = 16; off > 0; off >>= 1) exr += __shfl_xor_sync(FULL, exr, off);
            den += exr;

            int m = min(32, deg - c0);
            for (int j = 0; j < m; j += 2) {
                int   s0 = __shfl_sync(FULL, s,  j);
                float a0 = __shfl_sync(FULL, ex, j);
                int jn = (j + 1 < m) ? j + 1 : j;
                int   s1 = __shfl_sync(FULL, s,  jn);
                float a1 = (j + 1 < m) ? __shfl_sync(FULL, ex, jn) : 0.f;
                // (dummy shfl above keeps participation uniform; a1=0 kills the dup)
                int   ssel = half ? s1 : s0;
                float asel = half ? a1 : a0;
                float4 h = __ldg((const float4*)(hs + (size_t)ssel * CDIM) + part);
                acc.x = fmaf(asel, h.x, acc.x);
                acc.y = fmaf(asel, h.y, acc.y);
                acc.z = fmaf(asel, h.z, acc.z);
                acc.w = fmaf(asel, h.w, acc.w);
            }
        }
        // combine the two half-warp accumulators (channels are identical per part)
        acc.x += __shfl_xor_sync(FULL, acc.x, 16);
        acc.y += __shfl_xor_sync(FULL, acc.y, 16);
        acc.z += __shfl_xor_sync(FULL, acc.z, 16);
        acc.w += __shfl_xor_sync(FULL, acc.w, 16);
        float inv = 1.f / den;
        res.x = fmaf(acc.x, inv, res.x);
        res.y = fmaf(acc.y, inv, res.y);
        res.z = fmaf(acc.z, inv, res.z);
        res.w = fmaf(acc.w, inv, res.w);
    }
    if (ELUOUT) {
        res.x = (res.x > 0.f) ? res.x : expm1f(res.x);
        res.y = (res.y > 0.f) ? res.y : expm1f(res.y);
        res.z = (res.z > 0.f) ? res.z : expm1f(res.z);
        res.w = (res.w > 0.f) ? res.w : expm1f(res.w);
    }
    if (half == 0)
        ((float4*)(out + (size_t)w * CDIM))[part] = res;
}

// ------------------------- host orchestration -------------------------
extern "C" void kernel_launch(void* const* d_in, const int* in_sizes, int n_in,
                              void* d_out, int out_size)
{
    const float* xp   = (const float*)d_in[0];
    const float* xq   = (const float*)d_in[1];
    const int*   pv_s = (const int*)d_in[2];
    const int*   pv_d = (const int*)d_in[3];
    const int*   vp_s = (const int*)d_in[4];
    const int*   vp_d = (const int*)d_in[5];
    const float* Wsrc = (const float*)d_in[6];
    const float* Wdst = (const float*)d_in[7];
    const float* asrc = (const float*)d_in[8];
    const float* adst = (const float*)d_in[9];
    const float* bias = (const float*)d_in[10];
    int E = in_sizes[2];

    float *hsP, *hsQ, *hp1, *hq1, *alsP, *aldP, *alsQ, *aldQ, *wvec;
    int *cntQ, *cntP, *rowQ, *rowP, *curQ, *curP, *partQ, *partP, *ssrc0, *ssrc1;
    cudaGetSymbolAddress((void**)&hsP,   g_hsP);
    cudaGetSymbolAddress((void**)&hsQ,   g_hsQ);
    cudaGetSymbolAddress((void**)&hp1,   g_hp1);
    cudaGetSymbolAddress((void**)&hq1,   g_hq1);
    cudaGetSymbolAddress((void**)&alsP,  g_alsP);
    cudaGetSymbolAddress((void**)&aldP,  g_aldP);
    cudaGetSymbolAddress((void**)&alsQ,  g_alsQ);
    cudaGetSymbolAddress((void**)&aldQ,  g_aldQ);
    cudaGetSymbolAddress((void**)&wvec,  g_wvec);
    cudaGetSymbolAddress((void**)&cntQ,  g_cntQ);
    cudaGetSymbolAddress((void**)&cntP,  g_cntP);
    cudaGetSymbolAddress((void**)&rowQ,  g_rowQ);
    cudaGetSymbolAddress((void**)&rowP,  g_rowP);
    cudaGetSymbolAddress((void**)&curQ,  g_curQ);
    cudaGetSymbolAddress((void**)&curP,  g_curP);
    cudaGetSymbolAddress((void**)&partQ, g_partQ);
    cudaGetSymbolAddress((void**)&partP, g_partP);
    cudaGetSymbolAddress((void**)&ssrc0, g_ssrc0);
    cudaGetSymbolAddress((void**)&ssrc1, g_ssrc1);

    float* outp = (float*)d_out;
    float* outq = (float*)d_out + (size_t)NP * CDIM;

    const unsigned gP  = (NP + 127) / 128, gQ = (NQ + 127) / 128;
    const unsigned gGP = (unsigned)(((long)NP * 32 + 255) / 256);
    const unsigned gGQ = (unsigned)(((long)NQ * 32 + 255) / 256);
    const unsigned gE2 = (2 * E + 255) / 256;

    // ---- CSR build (once; reused by both layers) ----
    zero_kernel<<<(NQPAD + NPPAD + 255) / 256, 256>>>(cntQ, cntP);
    hist_kernel<<<gE2, 256>>>(pv_d, vp_d, cntQ, cntP, E);
    scan_local_kernel<<<MQ, 256>>>(cntQ, rowQ, partQ);
    scan_local_kernel<<<MP, 256>>>(cntP, rowP, partP);
    scan_part_kernel<<<1, 1024>>>(partQ, MQ);
    scan_part_kernel<<<1, 1024>>>(partP, MP);
    scan_add_kernel<<<NQPAD / 256, 256>>>(rowQ, partQ, curQ, NQPAD);
    scan_add_kernel<<<NPPAD / 256, 256>>>(rowP, partP, curP, NPPAD);
    scatter_kernel<<<gE2, 256>>>(pv_s, pv_d, vp_s, vp_d, curQ, curP, ssrc0, ssrc1, E);

    // ---- layer 0 ----
    wvec2_kernel<<<1, 128>>>(Wdst + 0 * 4096, Wdst + 1 * 4096, adst + 0 * 64, adst + 1 * 64, wvec);
    gemm_kernel<false><<<gP, 128>>>(xp, Wsrc + 0 * 4096, asrc + 0 * 64, wvec + 64,
                                    hsP, alsP, aldP, NP);
    gemm_kernel<false><<<gQ, 128>>>(xq, Wsrc + 1 * 4096, asrc + 1 * 64, wvec,
                                    hsQ, alsQ, aldQ, NQ);
    // conv1 first (hsQ L2-hot), then conv0
    gat_kernel<false><<<gGP, 256>>>(rowP, cntP, ssrc1, alsQ, aldP, hsQ, bias + 1 * 64, hp1, NP);
    gat_kernel<false><<<gGQ, 256>>>(rowQ, cntQ, ssrc0, alsP, aldQ, hsP, bias + 0 * 64, hq1, NQ);

    // ---- layer 1 (ELU on load; ELU folded into output store) ----
    wvec2_kernel<<<1, 128>>>(Wdst + 2 * 4096, Wdst + 3 * 4096, adst + 2 * 64, adst + 3 * 64, wvec);
    gemm_kernel<true><<<gP, 128>>>(hp1, Wsrc + 2 * 4096, asrc + 2 * 64, wvec + 64,
                                   hsP, alsP, aldP, NP);
    gemm_kernel<true><<<gQ, 128>>>(hq1, Wsrc + 3 * 4096, asrc + 3 * 64, wvec,
                                   hsQ, alsQ, aldQ, NQ);
    gat_kernel<true><<<gGP, 256>>>(rowP, cntP, ssrc1, alsQ, aldP, hsQ, bias + 3 * 64, outp, NP);
    gat_kernel<true><<<gGQ, 256>>>(rowQ, cntQ, ssrc0, alsP, aldQ, hsP, bias + 2 * 64, outq, NQ);
}

// round 9
// speedup vs baseline: 1.3145x; 1.1452x over previous
#include <cuda_runtime.h>
#include <math.h>
#include <stdint.h>

#define NP 500000
#define NQ 200000
#define CDIM 64
#define EMAX 1200000

// padded sizes for the 1024-per-block scan
#define NQPAD 200704   // 196 * 1024
#define NPPAD 500736   // 489 * 1024
#define MQ 196
#define MP 489

// ------------------------- scratch (static device globals) -------------------------
__device__ float g_hsP[(size_t)NP * CDIM];
__device__ float g_hsQ[(size_t)NQ * CDIM];
__device__ float g_hp1[(size_t)NP * CDIM];
__device__ float g_hq1[(size_t)NQ * CDIM];
__device__ float g_alsP[NP], g_aldP[NP];
__device__ float g_alsQ[NQ], g_aldQ[NQ];
__device__ float g_wvec[128];
// CSR scratch
__device__ int g_cntQ[NQPAD], g_cntP[NPPAD];
__device__ int g_rowQ[NQPAD], g_rowP[NPPAD];
__device__ int g_curQ[NQPAD], g_curP[NPPAD];
__device__ int g_partQ[1024], g_partP[1024];
__device__ int g_ssrc0[EMAX];   // conv0 (P->Q): person srcs sorted by product dst
__device__ int g_ssrc1[EMAX];   // conv1 (Q->P): product srcs sorted by person dst

// ------------------------- f32x2 packed-FMA helpers -------------------------
__device__ __forceinline__ unsigned long long pack2(float lo, float hi) {
    unsigned long long r;
    asm("mov.b64 %0, {%1, %2};" : "=l"(r) : "f"(lo), "f"(hi));
    return r;
}
__device__ __forceinline__ void fma2(unsigned long long& acc, unsigned long long a,
                                     unsigned long long b) {
    asm("fma.rn.f32x2 %0, %1, %2, %0;" : "+l"(acc) : "l"(a), "l"(b));
}
__device__ __forceinline__ float2 unpack2(unsigned long long v) {
    float lo, hi;
    asm("mov.b64 {%0, %1}, %2;" : "=f"(lo), "=f"(hi) : "l"(v));
    return make_float2(lo, hi);
}

// ------------------------- CSR build kernels -------------------------
__global__ void zero_kernel(int* __restrict__ cQ, int* __restrict__ cP) {
    int i = blockIdx.x * blockDim.x + threadIdx.x;
    if (i < NQPAD) cQ[i] = 0;
    else if (i < NQPAD + NPPAD) cP[i - NQPAD] = 0;
}

__global__ void hist_kernel(const int* __restrict__ pv_d, const int* __restrict__ vp_d,
                            int* __restrict__ cntQ, int* __restrict__ cntP, int E) {
    int i = blockIdx.x * blockDim.x + threadIdx.x;
    if (i < E) atomicAdd(&cntQ[__ldg(&pv_d[i])], 1);
    else if (i < 2 * E) atomicAdd(&cntP[__ldg(&vp_d[i - E])], 1);
}

__global__ void scan_local_kernel(const int* __restrict__ cnt, int* __restrict__ row,
                                  int* __restrict__ part) {
    __shared__ int sm[256];
    int t = threadIdx.x;
    int base = blockIdx.x * 1024 + t * 4;
    int4 v = *(const int4*)(cnt + base);
    int tsum = v.x + v.y + v.z + v.w;
    sm[t] = tsum;
    __syncthreads();
    #pragma unroll
    for (int off = 1; off < 256; off <<= 1) {
        int add = (t >= off) ? sm[t - off] : 0;
        __syncthreads();
        sm[t] += add;
        __syncthreads();
    }
    int excl = sm[t] - tsum;
    int r1 = excl + v.x, r2 = r1 + v.y, r3 = r2 + v.z;
    *(int4*)(row + base) = make_int4(excl, r1, r2, r3);
    if (t == 255) part[blockIdx.x] = sm[255];
}

__global__ void scan_part_kernel(int* __restrict__ part, int M) {
    __shared__ int sm[1024];
    int t = threadIdx.x;
    int orig = (t < M) ? part[t] : 0;
    sm[t] = orig;
    __syncthreads();
    #pragma unroll
    for (int off = 1; off < 1024; off <<= 1) {
        int add = (t >= off) ? sm[t - off] : 0;
        __syncthreads();
        sm[t] += add;
        __syncthreads();
    }
    if (t < M) part[t] = sm[t] - orig;
}

__global__ void scan_add_kernel(int* __restrict__ row, const int* __restrict__ part,
                                int* __restrict__ cur, int Npad) {
    int i = blockIdx.x * blockDim.x + threadIdx.x;
    if (i >= Npad) return;
    int r = row[i] + __ldg(&part[i >> 10]);
    row[i] = r;
    cur[i] = r;
}

__global__ void scatter_kernel(const int* __restrict__ pv_s, const int* __restrict__ pv_d,
                               const int* __restrict__ vp_s, const int* __restrict__ vp_d,
                               int* __restrict__ curQ, int* __restrict__ curP,
                               int* __restrict__ ssrc0, int* __restrict__ ssrc1, int E) {
    int i = blockIdx.x * blockDim.x + threadIdx.x;
    if (i < E) {
        int pos = atomicAdd(&curQ[__ldg(&pv_d[i])], 1);
        ssrc0[pos] = __ldg(&pv_s[i]);
    } else if (i < 2 * E) {
        int j = i - E;
        int pos = atomicAdd(&curP[__ldg(&vp_d[j])], 1);
        ssrc1[pos] = __ldg(&vp_s[j]);
    }
}

// ------------------------- dense kernels (R2-proven) -------------------------
__global__ void wvec2_kernel(const float* __restrict__ Wd0, const float* __restrict__ Wd1,
                             const float* __restrict__ avd0, const float* __restrict__ avd1,
                             float* __restrict__ wvec) {
    int t = threadIdx.x;
    const float* W = (t < 64) ? Wd0 : Wd1;
    const float* a = (t < 64) ? avd0 : avd1;
    int k = t & 63;
    float s = 0.f;
    #pragma unroll
    for (int c = 0; c < CDIM; c++) s = fmaf(W[k * CDIM + c], a[c], s);
    wvec[t] = s;
}

template <bool ELU>
__global__ __launch_bounds__(128) void gemm_kernel(
    const float* __restrict__ X, const float* __restrict__ W,
    const float* __restrict__ avs, const float* __restrict__ wvec,
    float* __restrict__ H, float* __restrict__ als, float* __restrict__ ald, int N)
{
    __shared__ float xT[64 * 128];
    __shared__ float ws[64 * 64];
    const int tid  = threadIdx.x;
    const int row0 = blockIdx.x * 128;

    {
        const float4* Wv = (const float4*)W;
        float4* wsv = (float4*)ws;
        #pragma unroll
        for (int i = 0; i < 8; i++) wsv[i * 128 + tid] = Wv[i * 128 + tid];
    }
    {
        int row = row0 + tid;
        if (row < N) {
            const float4* Xv = (const float4*)(X + (size_t)row * CDIM);
            #pragma unroll
            for (int j = 0; j < 16; j++) {
                float4 v = Xv[j];
                if (ELU) {
                    v.x = (v.x > 0.f) ? v.x : expm1f(v.x);
                    v.y = (v.y > 0.f) ? v.y : expm1f(v.y);
                    v.z = (v.z > 0.f) ? v.z : expm1f(v.z);
                    v.w = (v.w > 0.f) ? v.w : expm1f(v.w);
                }
                xT[(4 * j + 0) * 128 + tid] = v.x;
                xT[(4 * j + 1) * 128 + tid] = v.y;
                xT[(4 * j + 2) * 128 + tid] = v.z;
                xT[(4 * j + 3) * 128 + tid] = v.w;
            }
        } else {
            #pragma unroll
            for (int j = 0; j < 64; j++) xT[j * 128 + tid] = 0.f;
        }
    }
    __syncthreads();

    const int ty = tid >> 3;
    const int tx = tid & 7;
    unsigned long long acc[8][4];
    #pragma unroll
    for (int i = 0; i < 8; i++)
        #pragma unroll
        for (int j = 0; j < 4; j++) acc[i][j] = 0ull;

    #pragma unroll 4
    for (int k = 0; k < 64; k++) {
        float4 a0 = *(const float4*)&xT[k * 128 + ty * 8];
        float4 a1 = *(const float4*)&xT[k * 128 + ty * 8 + 4];
        float4 b0 = *(const float4*)&ws[k * 64 + tx * 8];
        float4 b1 = *(const float4*)&ws[k * 64 + tx * 8 + 4];
        unsigned long long bp[4] = {pack2(b0.x, b0.y), pack2(b0.z, b0.w),
                                    pack2(b1.x, b1.y), pack2(b1.z, b1.w)};
        float a[8] = {a0.x, a0.y, a0.z, a0.w, a1.x, a1.y, a1.z, a1.w};
        #pragma unroll
        for (int i = 0; i < 8; i++) {
            unsigned long long ap = pack2(a[i], a[i]);
            #pragma unroll
            for (int j = 0; j < 4; j++) fma2(acc[i][j], ap, bp[j]);
        }
    }

    unsigned long long avp[4];
    {
        float4 av0 = __ldg((const float4*)avs + tx * 2);
        float4 av1 = __ldg((const float4*)avs + tx * 2 + 1);
        avp[0] = pack2(av0.x, av0.y); avp[1] = pack2(av0.z, av0.w);
        avp[2] = pack2(av1.x, av1.y); avp[3] = pack2(av1.z, av1.w);
    }

    #pragma unroll
    for (int i = 0; i < 8; i++) {
        int row = row0 + ty * 8 + i;
        unsigned long long alp = 0ull;
        #pragma unroll
        for (int j = 0; j < 4; j++) fma2(alp, acc[i][j], avp[j]);
        float2 f = unpack2(alp);
        float al = f.x + f.y;
        al += __shfl_down_sync(0xffffffffu, al, 4);
        al += __shfl_down_sync(0xffffffffu, al, 2);
        al += __shfl_down_sync(0xffffffffu, al, 1);
        if (row < N) {
            ulonglong2* Hp = (ulonglong2*)(H + (size_t)row * CDIM + tx * 8);
            Hp[0] = make_ulonglong2(acc[i][0], acc[i][1]);
            Hp[1] = make_ulonglong2(acc[i][2], acc[i][3]);
            if (tx == 0) als[row] = al;
        }
    }

    {
        float s = 0.f;
        #pragma unroll
        for (int k = 0; k < 64; k++) s = fmaf(xT[k * 128 + tid], __ldg(&wvec[k]), s);
        int row = row0 + tid;
        if (row < N) ald[row] = s;
    }
}

// ---- CSR GAT: 2 rows per warp (16 lanes x float4 each), uniform control flow ----
// out[d] = (elu?)( bias + (1/Σex)·Σ ex_e·hs[src_e] ),  ex = exp(lrelu(als[src]+ald[d]))
// Chunk loop runs to degmax = max(deg0,deg1) (warp-uniform); padding lanes carry
// ex=0, s=0 (row 0 goes L1-hot). All shfls width-16 under uniform bounds.
template <bool ELUOUT>
__global__ __launch_bounds__(256) void gat_kernel(
    const int* __restrict__ row, const int* __restrict__ cnt, const int* __restrict__ ssrc,
    const float* __restrict__ als, const float* __restrict__ ald,
    const float* __restrict__ hs, const float* __restrict__ bias,
    float* __restrict__ out, int Nd)
{
    const unsigned FULL = 0xffffffffu;
    int w = (blockIdx.x * blockDim.x + threadIdx.x) >> 5;
    int r0 = w * 2;
    if (r0 >= Nd) return;
    const int lane = threadIdx.x & 31;
    const int half = lane >> 4;       // which row of the pair
    const int part = lane & 15;       // float4 index within the row

    int myrow = r0 + half;
    bool rowvalid = (myrow < Nd);
    int myr = rowvalid ? myrow : r0;             // clamp for safe loads
    int start = __ldg(&row[myr]);
    int deg   = rowvalid ? __ldg(&cnt[myr]) : 0;
    float aldv = __ldg(&ald[myr]);
    float4 res = __ldg((const float4*)bias + part);

    // warp-uniform max degree over the pair
    int degmax = max(deg, __shfl_xor_sync(FULL, deg, 16));

    float4 acc = make_float4(0.f, 0.f, 0.f, 0.f);
    float den = 0.f;
    for (int c0 = 0; c0 < degmax; c0 += 16) {
        int e = c0 + part;
        int s = 0; float ex = 0.f;
        if (e < deg) {
            s = __ldg(&ssrc[start + e]);
            float v = __ldg(&als[s]) + aldv;
            v = (v >= 0.f) ? v : 0.2f * v;
            ex = __expf(fminf(v, 80.f));
        }
        // den partial: reduce over my 16-lane half (convergent, uniform)
        float exr = ex;
        #pragma unroll
        for (int off = 8; off > 0; off >>= 1) exr += __shfl_xor_sync(FULL, exr, off, 16);
        den += exr;

        int m = min(16, degmax - c0);   // warp-uniform
        int j = 0;
        for (; j + 2 <= m; j += 2) {
            int   s0 = __shfl_sync(FULL, s,  j,     16);
            float a0 = __shfl_sync(FULL, ex, j,     16);
            int   s1 = __shfl_sync(FULL, s,  j + 1, 16);
            float a1 = __shfl_sync(FULL, ex, j + 1, 16);
            float4 h0 = __ldg((const float4*)(hs + (size_t)s0 * CDIM) + part);
            float4 h1 = __ldg((const float4*)(hs + (size_t)s1 * CDIM) + part);
            acc.x = fmaf(a0, h0.x, acc.x); acc.y = fmaf(a0, h0.y, acc.y);
            acc.z = fmaf(a0, h0.z, acc.z); acc.w = fmaf(a0, h0.w, acc.w);
            acc.x = fmaf(a1, h1.x, acc.x); acc.y = fmaf(a1, h1.y, acc.y);
            acc.z = fmaf(a1, h1.z, acc.z); acc.w = fmaf(a1, h1.w, acc.w);
        }
        if (j < m) {
            int   s0 = __shfl_sync(FULL, s,  j, 16);
            float a0 = __shfl_sync(FULL, ex, j, 16);
            float4 h0 = __ldg((const float4*)(hs + (size_t)s0 * CDIM) + part);
            acc.x = fmaf(a0, h0.x, acc.x); acc.y = fmaf(a0, h0.y, acc.y);
            acc.z = fmaf(a0, h0.z, acc.z); acc.w = fmaf(a0, h0.w, acc.w);
        }
    }
    float inv = (den > 0.f) ? (1.f / den) : 0.f;
    res.x = fmaf(acc.x, inv, res.x);
    res.y = fmaf(acc.y, inv, res.y);
    res.z = fmaf(acc.z, inv, res.z);
    res.w = fmaf(acc.w, inv, res.w);

    if (ELUOUT) {
        res.x = (res.x > 0.f) ? res.x : expm1f(res.x);
        res.y = (res.y > 0.f) ? res.y : expm1f(res.y);
        res.z = (res.z > 0.f) ? res.z : expm1f(res.z);
        res.w = (res.w > 0.f) ? res.w : expm1f(res.w);
    }
    if (rowvalid)
        ((float4*)(out + (size_t)myrow * CDIM))[part] = res;
}

// ------------------------- host orchestration -------------------------
extern "C" void kernel_launch(void* const* d_in, const int* in_sizes, int n_in,
                              void* d_out, int out_size)
{
    const float* xp   = (const float*)d_in[0];
    const float* xq   = (const float*)d_in[1];
    const int*   pv_s = (const int*)d_in[2];
    const int*   pv_d = (const int*)d_in[3];
    const int*   vp_s = (const int*)d_in[4];
    const int*   vp_d = (const int*)d_in[5];
    const float* Wsrc = (const float*)d_in[6];
    const float* Wdst = (const float*)d_in[7];
    const float* asrc = (const float*)d_in[8];
    const float* adst = (const float*)d_in[9];
    const float* bias = (const float*)d_in[10];
    int E = in_sizes[2];

    float *hsP, *hsQ, *hp1, *hq1, *alsP, *aldP, *alsQ, *aldQ, *wvec;
    int *cntQ, *cntP, *rowQ, *rowP, *curQ, *curP, *partQ, *partP, *ssrc0, *ssrc1;
    cudaGetSymbolAddress((void**)&hsP,   g_hsP);
    cudaGetSymbolAddress((void**)&hsQ,   g_hsQ);
    cudaGetSymbolAddress((void**)&hp1,   g_hp1);
    cudaGetSymbolAddress((void**)&hq1,   g_hq1);
    cudaGetSymbolAddress((void**)&alsP,  g_alsP);
    cudaGetSymbolAddress((void**)&aldP,  g_aldP);
    cudaGetSymbolAddress((void**)&alsQ,  g_alsQ);
    cudaGetSymbolAddress((void**)&aldQ,  g_aldQ);
    cudaGetSymbolAddress((void**)&wvec,  g_wvec);
    cudaGetSymbolAddress((void**)&cntQ,  g_cntQ);
    cudaGetSymbolAddress((void**)&cntP,  g_cntP);
    cudaGetSymbolAddress((void**)&rowQ,  g_rowQ);
    cudaGetSymbolAddress((void**)&rowP,  g_rowP);
    cudaGetSymbolAddress((void**)&curQ,  g_curQ);
    cudaGetSymbolAddress((void**)&curP,  g_curP);
    cudaGetSymbolAddress((void**)&partQ, g_partQ);
    cudaGetSymbolAddress((void**)&partP, g_partP);
    cudaGetSymbolAddress((void**)&ssrc0, g_ssrc0);
    cudaGetSymbolAddress((void**)&ssrc1, g_ssrc1);

    float* outp = (float*)d_out;
    float* outq = (float*)d_out + (size_t)NP * CDIM;

    const unsigned gP  = (NP + 127) / 128, gQ = (NQ + 127) / 128;
    const unsigned gGP = (unsigned)((((long)(NP + 1) / 2) * 32 + 255) / 256);
    const unsigned gGQ = (unsigned)((((long)(NQ + 1) / 2) * 32 + 255) / 256);
    const unsigned gE2 = (2 * E + 255) / 256;

    // ---- CSR build (once; reused by both layers) ----
    zero_kernel<<<(NQPAD + NPPAD + 255) / 256, 256>>>(cntQ, cntP);
    hist_kernel<<<gE2, 256>>>(pv_d, vp_d, cntQ, cntP, E);
    scan_local_kernel<<<MQ, 256>>>(cntQ, rowQ, partQ);
    scan_local_kernel<<<MP, 256>>>(cntP, rowP, partP);
    scan_part_kernel<<<1, 1024>>>(partQ, MQ);
    scan_part_kernel<<<1, 1024>>>(partP, MP);
    scan_add_kernel<<<NQPAD / 256, 256>>>(rowQ, partQ, curQ, NQPAD);
    scan_add_kernel<<<NPPAD / 256, 256>>>(rowP, partP, curP, NPPAD);
    scatter_kernel<<<gE2, 256>>>(pv_s, pv_d, vp_s, vp_d, curQ, curP, ssrc0, ssrc1, E);

    // ---- layer 0 ----
    wvec2_kernel<<<1, 128>>>(Wdst + 0 * 4096, Wdst + 1 * 4096, adst + 0 * 64, adst + 1 * 64, wvec);
    gemm_kernel<false><<<gP, 128>>>(xp, Wsrc + 0 * 4096, asrc + 0 * 64, wvec + 64,
                                    hsP, alsP, aldP, NP);
    gemm_kernel<false><<<gQ, 128>>>(xq, Wsrc + 1 * 4096, asrc + 1 * 64, wvec,
                                    hsQ, alsQ, aldQ, NQ);
    // conv1 first (hsQ L2-hot), then conv0
    gat_kernel<false><<<gGP, 256>>>(rowP, cntP, ssrc1, alsQ, aldP, hsQ, bias + 1 * 64, hp1, NP);
    gat_kernel<false><<<gGQ, 256>>>(rowQ, cntQ, ssrc0, alsP, aldQ, hsP, bias + 0 * 64, hq1, NQ);

    // ---- layer 1 (ELU on load; ELU folded into output store) ----
    wvec2_kernel<<<1, 128>>>(Wdst + 2 * 4096, Wdst + 3 * 4096, adst + 2 * 64, adst + 3 * 64, wvec);
    gemm_kernel<true><<<gP, 128>>>(hp1, Wsrc + 2 * 4096, asrc + 2 * 64, wvec + 64,
                                   hsP, alsP, aldP, NP);
    gemm_kernel<true><<<gQ, 128>>>(hq1, Wsrc + 3 * 4096, asrc + 3 * 64, wvec,
                                   hsQ, alsQ, aldQ, NQ);
    gat_kernel<true><<<gGP, 256>>>(rowP, cntP, ssrc1, alsQ, aldP, hsQ, bias + 3 * 64, outp, NP);
    gat_kernel<true><<<gGQ, 256>>>(rowQ, cntQ, ssrc0, alsP, aldQ, hsP, bias + 2 * 64, outq, NQ);
}

// round 10
// speedup vs baseline: 1.3823x; 1.0516x over previous
#include <cuda_runtime.h>
#include <math.h>
#include <stdint.h>

#define NP 500000
#define NQ 200000
#define CDIM 64
#define EMAX 1200000

// padded sizes for the 1024-per-block scan
#define NQPAD 200704   // 196 * 1024
#define NPPAD 500736   // 489 * 1024
#define MQ 196
#define MP 489

// ------------------------- scratch (static device globals) -------------------------
__device__ float g_hsP[(size_t)NP * CDIM];
__device__ float g_hsQ[(size_t)NQ * CDIM];
__device__ float g_hp1[(size_t)NP * CDIM];
__device__ float g_hq1[(size_t)NQ * CDIM];
__device__ float g_alsP[NP], g_aldP[NP];
__device__ float g_alsQ[NQ], g_aldQ[NQ];
__device__ float g_wvec[128];
// CSR scratch
__device__ int g_cntQ[NQPAD], g_cntP[NPPAD];
__device__ int g_rowQ[NQPAD], g_rowP[NPPAD];
__device__ int g_curQ[NQPAD], g_curP[NPPAD];
__device__ int g_partQ[1024], g_partP[1024];
__device__ int g_ssrc0[EMAX];   // conv0 (P->Q): person srcs sorted by product dst
__device__ int g_ssrc1[EMAX];   // conv1 (Q->P): product srcs sorted by person dst

// ------------------------- f32x2 packed-FMA helpers -------------------------
__device__ __forceinline__ unsigned long long pack2(float lo, float hi) {
    unsigned long long r;
    asm("mov.b64 %0, {%1, %2};" : "=l"(r) : "f"(lo), "f"(hi));
    return r;
}
__device__ __forceinline__ void fma2(unsigned long long& acc, unsigned long long a,
                                     unsigned long long b) {
    asm("fma.rn.f32x2 %0, %1, %2, %0;" : "+l"(acc) : "l"(a), "l"(b));
}
__device__ __forceinline__ float2 unpack2(unsigned long long v) {
    float lo, hi;
    asm("mov.b64 {%0, %1}, %2;" : "=f"(lo), "=f"(hi) : "l"(v));
    return make_float2(lo, hi);
}

// ------------------------- CSR build kernels -------------------------
__global__ void zero_kernel(int* __restrict__ cQ, int* __restrict__ cP) {
    int i = blockIdx.x * blockDim.x + threadIdx.x;
    if (i < NQPAD) cQ[i] = 0;
    else if (i < NQPAD + NPPAD) cP[i - NQPAD] = 0;
}

__global__ void hist_kernel(const int* __restrict__ pv_d, const int* __restrict__ vp_d,
                            int* __restrict__ cntQ, int* __restrict__ cntP, int E) {
    int i = blockIdx.x * blockDim.x + threadIdx.x;
    if (i < E) atomicAdd(&cntQ[__ldg(&pv_d[i])], 1);
    else if (i < 2 * E) atomicAdd(&cntP[__ldg(&vp_d[i - E])], 1);
}

__global__ void scan_local_kernel(const int* __restrict__ cnt, int* __restrict__ row,
                                  int* __restrict__ part) {
    __shared__ int sm[256];
    int t = threadIdx.x;
    int base = blockIdx.x * 1024 + t * 4;
    int4 v = *(const int4*)(cnt + base);
    int tsum = v.x + v.y + v.z + v.w;
    sm[t] = tsum;
    __syncthreads();
    #pragma unroll
    for (int off = 1; off < 256; off <<= 1) {
        int add = (t >= off) ? sm[t - off] : 0;
        __syncthreads();
        sm[t] += add;
        __syncthreads();
    }
    int excl = sm[t] - tsum;
    int r1 = excl + v.x, r2 = r1 + v.y, r3 = r2 + v.z;
    *(int4*)(row + base) = make_int4(excl, r1, r2, r3);
    if (t == 255) part[blockIdx.x] = sm[255];
}

__global__ void scan_part_kernel(int* __restrict__ part, int M) {
    __shared__ int sm[1024];
    int t = threadIdx.x;
    int orig = (t < M) ? part[t] : 0;
    sm[t] = orig;
    __syncthreads();
    #pragma unroll
    for (int off = 1; off < 1024; off <<= 1) {
        int add = (t >= off) ? sm[t - off] : 0;
        __syncthreads();
        sm[t] += add;
        __syncthreads();
    }
    if (t < M) part[t] = sm[t] - orig;
}

__global__ void scan_add_kernel(int* __restrict__ row, const int* __restrict__ part,
                                int* __restrict__ cur, int Npad) {
    int i = blockIdx.x * blockDim.x + threadIdx.x;
    if (i >= Npad) return;
    int r = row[i] + __ldg(&part[i >> 10]);
    row[i] = r;
    cur[i] = r;
}

__global__ void scatter_kernel(const int* __restrict__ pv_s, const int* __restrict__ pv_d,
                               const int* __restrict__ vp_s, const int* __restrict__ vp_d,
                               int* __restrict__ curQ, int* __restrict__ curP,
                               int* __restrict__ ssrc0, int* __restrict__ ssrc1, int E) {
    int i = blockIdx.x * blockDim.x + threadIdx.x;
    if (i < E) {
        int pos = atomicAdd(&curQ[__ldg(&pv_d[i])], 1);
        ssrc0[pos] = __ldg(&pv_s[i]);
    } else if (i < 2 * E) {
        int j = i - E;
        int pos = atomicAdd(&curP[__ldg(&vp_d[j])], 1);
        ssrc1[pos] = __ldg(&vp_s[j]);
    }
}

// ------------------------- dense kernels (R2-proven) -------------------------
__global__ void wvec2_kernel(const float* __restrict__ Wd0, const float* __restrict__ Wd1,
                             const float* __restrict__ avd0, const float* __restrict__ avd1,
                             float* __restrict__ wvec) {
    int t = threadIdx.x;
    const float* W = (t < 64) ? Wd0 : Wd1;
    const float* a = (t < 64) ? avd0 : avd1;
    int k = t & 63;
    float s = 0.f;
    #pragma unroll
    for (int c = 0; c < CDIM; c++) s = fmaf(W[k * CDIM + c], a[c], s);
    wvec[t] = s;
}

template <bool ELU>
__global__ __launch_bounds__(128) void gemm_kernel(
    const float* __restrict__ X, const float* __restrict__ W,
    const float* __restrict__ avs, const float* __restrict__ wvec,
    float* __restrict__ H, float* __restrict__ als, float* __restrict__ ald, int N)
{
    __shared__ float xT[64 * 128];
    __shared__ float ws[64 * 64];
    const int tid  = threadIdx.x;
    const int row0 = blockIdx.x * 128;

    {
        const float4* Wv = (const float4*)W;
        float4* wsv = (float4*)ws;
        #pragma unroll
        for (int i = 0; i < 8; i++) wsv[i * 128 + tid] = Wv[i * 128 + tid];
    }
    {
        int row = row0 + tid;
        if (row < N) {
            const float4* Xv = (const float4*)(X + (size_t)row * CDIM);
            #pragma unroll
            for (int j = 0; j < 16; j++) {
                float4 v = Xv[j];
                if (ELU) {
                    v.x = (v.x > 0.f) ? v.x : expm1f(v.x);
                    v.y = (v.y > 0.f) ? v.y : expm1f(v.y);
                    v.z = (v.z > 0.f) ? v.z : expm1f(v.z);
                    v.w = (v.w > 0.f) ? v.w : expm1f(v.w);
                }
                xT[(4 * j + 0) * 128 + tid] = v.x;
                xT[(4 * j + 1) * 128 + tid] = v.y;
                xT[(4 * j + 2) * 128 + tid] = v.z;
                xT[(4 * j + 3) * 128 + tid] = v.w;
            }
        } else {
            #pragma unroll
            for (int j = 0; j < 64; j++) xT[j * 128 + tid] = 0.f;
        }
    }
    __syncthreads();

    const int ty = tid >> 3;
    const int tx = tid & 7;
    unsigned long long acc[8][4];
    #pragma unroll
    for (int i = 0; i < 8; i++)
        #pragma unroll
        for (int j = 0; j < 4; j++) acc[i][j] = 0ull;

    #pragma unroll 4
    for (int k = 0; k < 64; k++) {
        float4 a0 = *(const float4*)&xT[k * 128 + ty * 8];
        float4 a1 = *(const float4*)&xT[k * 128 + ty * 8 + 4];
        float4 b0 = *(const float4*)&ws[k * 64 + tx * 8];
        float4 b1 = *(const float4*)&ws[k * 64 + tx * 8 + 4];
        unsigned long long bp[4] = {pack2(b0.x, b0.y), pack2(b0.z, b0.w),
                                    pack2(b1.x, b1.y), pack2(b1.z, b1.w)};
        float a[8] = {a0.x, a0.y, a0.z, a0.w, a1.x, a1.y, a1.z, a1.w};
        #pragma unroll
        for (int i = 0; i < 8; i++) {
            unsigned long long ap = pack2(a[i], a[i]);
            #pragma unroll
            for (int j = 0; j < 4; j++) fma2(acc[i][j], ap, bp[j]);
        }
    }

    unsigned long long avp[4];
    {
        float4 av0 = __ldg((const float4*)avs + tx * 2);
        float4 av1 = __ldg((const float4*)avs + tx * 2 + 1);
        avp[0] = pack2(av0.x, av0.y); avp[1] = pack2(av0.z, av0.w);
        avp[2] = pack2(av1.x, av1.y); avp[3] = pack2(av1.z, av1.w);
    }

    #pragma unroll
    for (int i = 0; i < 8; i++) {
        int row = row0 + ty * 8 + i;
        unsigned long long alp = 0ull;
        #pragma unroll
        for (int j = 0; j < 4; j++) fma2(alp, acc[i][j], avp[j]);
        float2 f = unpack2(alp);
        float al = f.x + f.y;
        al += __shfl_down_sync(0xffffffffu, al, 4);
        al += __shfl_down_sync(0xffffffffu, al, 2);
        al += __shfl_down_sync(0xffffffffu, al, 1);
        if (row < N) {
            ulonglong2* Hp = (ulonglong2*)(H + (size_t)row * CDIM + tx * 8);
            Hp[0] = make_ulonglong2(acc[i][0], acc[i][1]);
            Hp[1] = make_ulonglong2(acc[i][2], acc[i][3]);
            if (tx == 0) als[row] = al;
        }
    }

    {
        float s = 0.f;
        #pragma unroll
        for (int k = 0; k < 64; k++) s = fmaf(xT[k * 128 + tid], __ldg(&wvec[k]), s);
        int row = row0 + tid;
        if (row < N) ald[row] = s;
    }
}

// ---- CSR GAT: 4 rows per warp (8 lanes x 2 float4 each), uniform control flow ----
// out[d] = (elu?)( bias + (1/Σex)·Σ ex_e·hs[src_e] ),  ex = exp(lrelu(als[src]+ald[d]))
// Chunk = 8 edges; loop bound degmax = max over the 4 rows (warp-uniform).
// Padding lanes carry ex=0, s=0 (hs row 0 goes L1-hot). All shfls width-8.
template <bool ELUOUT>
__global__ __launch_bounds__(256) void gat_kernel(
    const int* __restrict__ row, const int* __restrict__ cnt, const int* __restrict__ ssrc,
    const float* __restrict__ als, const float* __restrict__ ald,
    const float* __restrict__ hs, const float* __restrict__ bias,
    float* __restrict__ out, int Nd)
{
    const unsigned FULL = 0xffffffffu;
    int w = (blockIdx.x * blockDim.x + threadIdx.x) >> 5;
    int r0 = w * 4;
    if (r0 >= Nd) return;
    const int lane = threadIdx.x & 31;
    const int qg   = lane >> 3;      // which row of the quad (0..3)
    const int part = lane & 7;       // float4 slots part and part+8

    int myrow = r0 + qg;
    bool rowvalid = (myrow < Nd);
    int myr = rowvalid ? myrow : r0;             // clamp for safe loads
    int start = __ldg(&row[myr]);
    int deg   = rowvalid ? __ldg(&cnt[myr]) : 0;
    float aldv = __ldg(&ald[myr]);
    float4 res0 = __ldg((const float4*)bias + part);
    float4 res1 = __ldg((const float4*)bias + part + 8);

    // warp-uniform max degree over the quad
    int degmax = max(deg, __shfl_xor_sync(FULL, deg, 8));
    degmax = max(degmax, __shfl_xor_sync(FULL, degmax, 16));

    float4 acc0 = make_float4(0.f, 0.f, 0.f, 0.f);
    float4 acc1 = make_float4(0.f, 0.f, 0.f, 0.f);
    float den = 0.f;
    for (int c0 = 0; c0 < degmax; c0 += 8) {
        int e = c0 + part;
        int s = 0; float ex = 0.f;
        if (e < deg) {
            s = __ldg(&ssrc[start + e]);
            float v = __ldg(&als[s]) + aldv;
            v = (v >= 0.f) ? v : 0.2f * v;
            ex = __expf(fminf(v, 80.f));
        }
        // den partial: reduce over my 8-lane group (convergent, uniform)
        float exr = ex;
        #pragma unroll
        for (int off = 4; off > 0; off >>= 1) exr += __shfl_xor_sync(FULL, exr, off, 8);
        den += exr;

        int m = min(8, degmax - c0);   // warp-uniform
        int j = 0;
        for (; j + 2 <= m; j += 2) {
            int   s0 = __shfl_sync(FULL, s,  j,     8);
            float a0 = __shfl_sync(FULL, ex, j,     8);
            int   s1 = __shfl_sync(FULL, s,  j + 1, 8);
            float a1 = __shfl_sync(FULL, ex, j + 1, 8);
            const float4* h0p = (const float4*)(hs + (size_t)s0 * CDIM);
            const float4* h1p = (const float4*)(hs + (size_t)s1 * CDIM);
            float4 h0a = __ldg(h0p + part);
            float4 h0b = __ldg(h0p + part + 8);
            float4 h1a = __ldg(h1p + part);
            float4 h1b = __ldg(h1p + part + 8);
            acc0.x = fmaf(a0, h0a.x, acc0.x); acc0.y = fmaf(a0, h0a.y, acc0.y);
            acc0.z = fmaf(a0, h0a.z, acc0.z); acc0.w = fmaf(a0, h0a.w, acc0.w);
            acc1.x = fmaf(a0, h0b.x, acc1.x); acc1.y = fmaf(a0, h0b.y, acc1.y);
            acc1.z = fmaf(a0, h0b.z, acc1.z); acc1.w = fmaf(a0, h0b.w, acc1.w);
            acc0.x = fmaf(a1, h1a.x, acc0.x); acc0.y = fmaf(a1, h1a.y, acc0.y);
            acc0.z = fmaf(a1, h1a.z, acc0.z); acc0.w = fmaf(a1, h1a.w, acc0.w);
            acc1.x = fmaf(a1, h1b.x, acc1.x); acc1.y = fmaf(a1, h1b.y, acc1.y);
            acc1.z = fmaf(a1, h1b.z, acc1.z); acc1.w = fmaf(a1, h1b.w, acc1.w);
        }
        if (j < m) {
            int   s0 = __shfl_sync(FULL, s,  j, 8);
            float a0 = __shfl_sync(FULL, ex, j, 8);
            const float4* h0p = (const float4*)(hs + (size_t)s0 * CDIM);
            float4 h0a = __ldg(h0p + part);
            float4 h0b = __ldg(h0p + part + 8);
            acc0.x = fmaf(a0, h0a.x, acc0.x); acc0.y = fmaf(a0, h0a.y, acc0.y);
            acc0.z = fmaf(a0, h0a.z, acc0.z); acc0.w = fmaf(a0, h0a.w, acc0.w);
            acc1.x = fmaf(a0, h0b.x, acc1.x); acc1.y = fmaf(a0, h0b.y, acc1.y);
            acc1.z = fmaf(a0, h0b.z, acc1.z); acc1.w = fmaf(a0, h0b.w, acc1.w);
        }
    }
    float inv = (den > 0.f) ? (1.f / den) : 0.f;
    res0.x = fmaf(acc0.x, inv, res0.x); res0.y = fmaf(acc0.y, inv, res0.y);
    res0.z = fmaf(acc0.z, inv, res0.z); res0.w = fmaf(acc0.w, inv, res0.w);
    res1.x = fmaf(acc1.x, inv, res1.x); res1.y = fmaf(acc1.y, inv, res1.y);
    res1.z = fmaf(acc1.z, inv, res1.z); res1.w = fmaf(acc1.w, inv, res1.w);

    if (ELUOUT) {
        res0.x = (res0.x > 0.f) ? res0.x : expm1f(res0.x);
        res0.y = (res0.y > 0.f) ? res0.y : expm1f(res0.y);
        res0.z = (res0.z > 0.f) ? res0.z : expm1f(res0.z);
        res0.w = (res0.w > 0.f) ? res0.w : expm1f(res0.w);
        res1.x = (res1.x > 0.f) ? res1.x : expm1f(res1.x);
        res1.y = (res1.y > 0.f) ? res1.y : expm1f(res1.y);
        res1.z = (res1.z > 0.f) ? res1.z : expm1f(res1.z);
        res1.w = (res1.w > 0.f) ? res1.w : expm1f(res1.w);
    }
    if (rowvalid) {
        float4* op = (float4*)(out + (size_t)myrow * CDIM);
        op[part] = res0;
        op[part + 8] = res1;
    }
}

// ------------------------- host orchestration -------------------------
extern "C" void kernel_launch(void* const* d_in, const int* in_sizes, int n_in,
                              void* d_out, int out_size)
{
    const float* xp   = (const float*)d_in[0];
    const float* xq   = (const float*)d_in[1];
    const int*   pv_s = (const int*)d_in[2];
    const int*   pv_d = (const int*)d_in[3];
    const int*   vp_s = (const int*)d_in[4];
    const int*   vp_d = (const int*)d_in[5];
    const float* Wsrc = (const float*)d_in[6];
    const float* Wdst = (const float*)d_in[7];
    const float* asrc = (const float*)d_in[8];
    const float* adst = (const float*)d_in[9];
    const float* bias = (const float*)d_in[10];
    int E = in_sizes[2];

    float *hsP, *hsQ, *hp1, *hq1, *alsP, *aldP, *alsQ, *aldQ, *wvec;
    int *cntQ, *cntP, *rowQ, *rowP, *curQ, *curP, *partQ, *partP, *ssrc0, *ssrc1;
    cudaGetSymbolAddress((void**)&hsP,   g_hsP);
    cudaGetSymbolAddress((void**)&hsQ,   g_hsQ);
    cudaGetSymbolAddress((void**)&hp1,   g_hp1);
    cudaGetSymbolAddress((void**)&hq1,   g_hq1);
    cudaGetSymbolAddress((void**)&alsP,  g_alsP);
    cudaGetSymbolAddress((void**)&aldP,  g_aldP);
    cudaGetSymbolAddress((void**)&alsQ,  g_alsQ);
    cudaGetSymbolAddress((void**)&aldQ,  g_aldQ);
    cudaGetSymbolAddress((void**)&wvec,  g_wvec);
    cudaGetSymbolAddress((void**)&cntQ,  g_cntQ);
    cudaGetSymbolAddress((void**)&cntP,  g_cntP);
    cudaGetSymbolAddress((void**)&rowQ,  g_rowQ);
    cudaGetSymbolAddress((void**)&rowP,  g_rowP);
    cudaGetSymbolAddress((void**)&curQ,  g_curQ);
    cudaGetSymbolAddress((void**)&curP,  g_curP);
    cudaGetSymbolAddress((void**)&partQ, g_partQ);
    cudaGetSymbolAddress((void**)&partP, g_partP);
    cudaGetSymbolAddress((void**)&ssrc0, g_ssrc0);
    cudaGetSymbolAddress((void**)&ssrc1, g_ssrc1);

    float* outp = (float*)d_out;
    float* outq = (float*)d_out + (size_t)NP * CDIM;

    const unsigned gP  = (NP + 127) / 128, gQ = (NQ + 127) / 128;
    const unsigned gGP = (unsigned)((((long)(NP + 3) / 4) * 32 + 255) / 256);
    const unsigned gGQ = (unsigned)((((long)(NQ + 3) / 4) * 32 + 255) / 256);
    const unsigned gE2 = (2 * E + 255) / 256;

    // ---- CSR build (once; reused by both layers) ----
    zero_kernel<<<(NQPAD + NPPAD + 255) / 256, 256>>>(cntQ, cntP);
    hist_kernel<<<gE2, 256>>>(pv_d, vp_d, cntQ, cntP, E);
    scan_local_kernel<<<MQ, 256>>>(cntQ, rowQ, partQ);
    scan_local_kernel<<<MP, 256>>>(cntP, rowP, partP);
    scan_part_kernel<<<1, 1024>>>(partQ, MQ);
    scan_part_kernel<<<1, 1024>>>(partP, MP);
    scan_add_kernel<<<NQPAD / 256, 256>>>(rowQ, partQ, curQ, NQPAD);
    scan_add_kernel<<<NPPAD / 256, 256>>>(rowP, partP, curP, NPPAD);
    scatter_kernel<<<gE2, 256>>>(pv_s, pv_d, vp_s, vp_d, curQ, curP, ssrc0, ssrc1, E);

    // ---- layer 0 ----
    wvec2_kernel<<<1, 128>>>(Wdst + 0 * 4096, Wdst + 1 * 4096, adst + 0 * 64, adst + 1 * 64, wvec);
    gemm_kernel<false><<<gP, 128>>>(xp, Wsrc + 0 * 4096, asrc + 0 * 64, wvec + 64,
                                    hsP, alsP, aldP, NP);
    gemm_kernel<false><<<gQ, 128>>>(xq, Wsrc + 1 * 4096, asrc + 1 * 64, wvec,
                                    hsQ, alsQ, aldQ, NQ);
    // conv1 first (hsQ L2-hot), then conv0
    gat_kernel<false><<<gGP, 256>>>(rowP, cntP, ssrc1, alsQ, aldP, hsQ, bias + 1 * 64, hp1, NP);
    gat_kernel<false><<<gGQ, 256>>>(rowQ, cntQ, ssrc0, alsP, aldQ, hsP, bias + 0 * 64, hq1, NQ);

    // ---- layer 1 (ELU on load; ELU folded into output store) ----
    wvec2_kernel<<<1, 128>>>(Wdst + 2 * 4096, Wdst + 3 * 4096, adst + 2 * 64, adst + 3 * 64, wvec);
    gemm_kernel<true><<<gP, 128>>>(hp1, Wsrc + 2 * 4096, asrc + 2 * 64, wvec + 64,
                                   hsP, alsP, aldP, NP);
    gemm_kernel<true><<<gQ, 128>>>(hq1, Wsrc + 3 * 4096, asrc + 3 * 64, wvec,
                                   hsQ, alsQ, aldQ, NQ);
    gat_kernel<true><<<gGP, 256>>>(rowP, cntP, ssrc1, alsQ, aldP, hsQ, bias + 3 * 64, outp, NP);
    gat_kernel<true><<<gGQ, 256>>>(rowQ, cntQ, ssrc0, alsP, aldQ, hsP, bias + 2 * 64, outq, NQ);
}